// round 1
// baseline (speedup 1.0000x reference)
#include <cuda_runtime.h>
#include <math.h>

#define NN   50000
#define EE   1600000
#define DIN  128
#define HIDD 128
#define DOUT 64
#define NLL  200000
#define NEG  0.2f

// ---------------- scratch (device globals; no allocation allowed) ----------------
__device__ float g_bufA[NN * HIDD];
__device__ float g_bufB[NN * HIDD];
__device__ float g_zbuf[NN * DOUT];
__device__ float g_as[NN];
__device__ float g_ad[NN];
__device__ float g_dinv[NN];
__device__ int   g_deg[NN];
__device__ int   g_cursor[NN];
__device__ int   g_rowptr[NN + 1];
__device__ int   g_csrc[EE];

__device__ __forceinline__ float lrelu(float v) { return v > 0.f ? v : NEG * v; }

// ---------------- CSR build ----------------
__global__ void zero_kernel() {
    int i = blockIdx.x * blockDim.x + threadIdx.x;
    if (i < NN) { g_deg[i] = 0; g_cursor[i] = 0; }
}

__global__ void count_deg_kernel(const int* __restrict__ dst) {
    int i = blockIdx.x * blockDim.x + threadIdx.x;
    if (i < EE) atomicAdd(&g_deg[dst[i]], 1);
}

__global__ void scan_kernel() {
    __shared__ int warp_sums[32];
    __shared__ int carry;
    int tid = threadIdx.x;
    if (tid == 0) carry = 0;
    __syncthreads();
    for (int base = 0; base < NN; base += 1024) {
        int i = base + tid;
        int v = (i < NN) ? g_deg[i] : 0;
        int x = v;
        #pragma unroll
        for (int o = 1; o < 32; o <<= 1) {
            int y = __shfl_up_sync(0xffffffffu, x, o);
            if ((tid & 31) >= o) x += y;
        }
        if ((tid & 31) == 31) warp_sums[tid >> 5] = x;
        __syncthreads();
        if (tid < 32) {
            int w = warp_sums[tid];
            #pragma unroll
            for (int o = 1; o < 32; o <<= 1) {
                int y = __shfl_up_sync(0xffffffffu, w, o);
                if (tid >= o) w += y;
            }
            warp_sums[tid] = w;
        }
        __syncthreads();
        int pref = (tid >= 32) ? warp_sums[(tid >> 5) - 1] : 0;
        int incl = x + pref;
        if (i < NN) g_rowptr[i] = incl - v + carry;
        int total = warp_sums[31];
        __syncthreads();
        if (tid == 0) carry += total;
        __syncthreads();
    }
    if (tid == 0) g_rowptr[NN] = carry;
}

__global__ void fill_csr_kernel(const int* __restrict__ src, const int* __restrict__ dst) {
    int i = blockIdx.x * blockDim.x + threadIdx.x;
    if (i < EE) {
        int d = dst[i];
        int pos = atomicAdd(&g_cursor[d], 1);
        g_csrc[g_rowptr[d] + pos] = src[i];
    }
}

__global__ void dinv_kernel() {
    int i = blockIdx.x * blockDim.x + threadIdx.x;
    if (i < NN) g_dinv[i] = rsqrtf((float)(g_rowptr[i + 1] - g_rowptr[i] + 1));
}

// ---------------- SGEMM: C[M,Ncols] = A[M,K] * B[K,Ncols] (row-major) ----------------
// BM=128, BN=64, BK=16, TM=TN=8, 128 threads.
__global__ void sgemm_kernel(int M, int Ncols, int K,
                             const float* __restrict__ A,
                             const float* __restrict__ B,
                             float* __restrict__ C) {
    const int BM = 128, BN = 64, BK = 16, TM = 8, TN = 8;
    const int tid = threadIdx.x;          // 128 threads
    const int block_row = blockIdx.x * BM;
    const int block_col = blockIdx.y * BN;
    __shared__ float As[BK][BM];
    __shared__ float Bs[BK][BN];
    const int tr = tid / (BN / TN);       // 0..15
    const int tc = tid % (BN / TN);       // 0..7
    float acc[TM][TN];
    #pragma unroll
    for (int i = 0; i < TM; i++)
        #pragma unroll
        for (int j = 0; j < TN; j++) acc[i][j] = 0.f;

    const int aRow  = tid / (BK / 4);     // 0..31
    const int aCol4 = tid % (BK / 4);     // 0..3
    const int bRow  = tid / (BN / 4);     // 0..7
    const int bCol4 = tid % (BN / 4);     // 0..15

    for (int k0 = 0; k0 < K; k0 += BK) {
        #pragma unroll
        for (int i = 0; i < 4; i++) {
            int r = aRow + i * 32;
            int grow = block_row + r;
            float4 v = make_float4(0.f, 0.f, 0.f, 0.f);
            if (grow < M)
                v = *reinterpret_cast<const float4*>(&A[(size_t)grow * K + k0 + aCol4 * 4]);
            As[aCol4 * 4 + 0][r] = v.x;
            As[aCol4 * 4 + 1][r] = v.y;
            As[aCol4 * 4 + 2][r] = v.z;
            As[aCol4 * 4 + 3][r] = v.w;
        }
        #pragma unroll
        for (int i = 0; i < 2; i++) {
            int r = bRow + i * 8;
            float4 v = *reinterpret_cast<const float4*>(
                &B[(size_t)(k0 + r) * Ncols + block_col + bCol4 * 4]);
            *reinterpret_cast<float4*>(&Bs[r][bCol4 * 4]) = v;
        }
        __syncthreads();
        #pragma unroll
        for (int kk = 0; kk < BK; kk++) {
            float ra[TM], rb[TN];
            #pragma unroll
            for (int i = 0; i < TM; i++) ra[i] = As[kk][tr * TM + i];
            #pragma unroll
            for (int j = 0; j < TN; j++) rb[j] = Bs[kk][tc * TN + j];
            #pragma unroll
            for (int i = 0; i < TM; i++)
                #pragma unroll
                for (int j = 0; j < TN; j++) acc[i][j] += ra[i] * rb[j];
        }
        __syncthreads();
    }
    #pragma unroll
    for (int i = 0; i < TM; i++) {
        int grow = block_row + tr * TM + i;
        if (grow < M) {
            #pragma unroll
            for (int j4 = 0; j4 < TN / 4; j4++) {
                float4 v = make_float4(acc[i][j4 * 4 + 0], acc[i][j4 * 4 + 1],
                                       acc[i][j4 * 4 + 2], acc[i][j4 * 4 + 3]);
                *reinterpret_cast<float4*>(
                    &C[(size_t)grow * Ncols + block_col + tc * TN + j4 * 4]) = v;
            }
        }
    }
}

// ---------------- per-node attention scores: as=h@a_s, ad=h@a_d ----------------
__global__ void scores_kernel(const float* __restrict__ h,
                              const float* __restrict__ avs,
                              const float* __restrict__ avd) {
    int warp = (blockIdx.x * blockDim.x + threadIdx.x) >> 5;
    int lane = threadIdx.x & 31;
    if (warp >= NN) return;
    const float4* h4 = reinterpret_cast<const float4*>(h);
    float4 hv = h4[(size_t)warp * 32 + lane];
    float4 sv = reinterpret_cast<const float4*>(avs)[lane];
    float4 dv = reinterpret_cast<const float4*>(avd)[lane];
    float s = hv.x * sv.x + hv.y * sv.y + hv.z * sv.z + hv.w * sv.w;
    float d = hv.x * dv.x + hv.y * dv.y + hv.z * dv.z + hv.w * dv.w;
    #pragma unroll
    for (int o = 16; o; o >>= 1) {
        s += __shfl_xor_sync(0xffffffffu, s, o);
        d += __shfl_xor_sync(0xffffffffu, d, o);
    }
    if (lane == 0) { g_as[warp] = s; g_ad[warp] = d; }
}

// ---------------- GAT aggregate (warp per dst node), fused softmax + bias + relu ----------------
__global__ void gat_agg_kernel(const float* __restrict__ h,
                               const float* __restrict__ bias,
                               float* __restrict__ out) {
    int warp = (blockIdx.x * blockDim.x + threadIdx.x) >> 5;
    int lane = threadIdx.x & 31;
    if (warp >= NN) return;
    int node = warp;
    int rs = g_rowptr[node], re = g_rowptr[node + 1];
    float adi = g_ad[node];
    float self_e = lrelu(g_as[node] + adi);

    // pass 1: max
    float m = self_e;
    for (int j = rs + lane; j < re; j += 32)
        m = fmaxf(m, lrelu(g_as[g_csrc[j]] + adi));
    #pragma unroll
    for (int o = 16; o; o >>= 1) m = fmaxf(m, __shfl_xor_sync(0xffffffffu, m, o));

    // pass 2: sum of exp
    float ssum = 0.f;
    for (int j = rs + lane; j < re; j += 32)
        ssum += __expf(lrelu(g_as[g_csrc[j]] + adi) - m);
    #pragma unroll
    for (int o = 16; o; o >>= 1) ssum += __shfl_xor_sync(0xffffffffu, ssum, o);
    ssum += __expf(self_e - m);

    // pass 3: weighted accumulate
    const float4* h4 = reinterpret_cast<const float4*>(h);
    float pself = __expf(self_e - m);
    float4 hv = h4[(size_t)node * 32 + lane];
    float4 acc = make_float4(pself * hv.x, pself * hv.y, pself * hv.z, pself * hv.w);
    for (int j = rs; j < re; j++) {
        int src = g_csrc[j];                       // uniform across warp
        float p = __expf(lrelu(g_as[src] + adi) - m);
        float4 v = h4[(size_t)src * 32 + lane];
        acc.x += p * v.x; acc.y += p * v.y; acc.z += p * v.z; acc.w += p * v.w;
    }
    float inv = 1.f / ssum;
    float4 bv = reinterpret_cast<const float4*>(bias)[lane];
    float4 o;
    o.x = fmaxf(acc.x * inv + bv.x, 0.f);
    o.y = fmaxf(acc.y * inv + bv.y, 0.f);
    o.z = fmaxf(acc.z * inv + bv.z, 0.f);
    o.w = fmaxf(acc.w * inv + bv.w, 0.f);
    reinterpret_cast<float4*>(out)[(size_t)node * 32 + lane] = o;
}

// ---------------- GCN aggregate (warp per dst node), OUT=64 (float2/lane) ----------------
__global__ void gcn_agg_kernel(const float* __restrict__ g,
                               const float* __restrict__ bias,
                               float* __restrict__ z) {
    int warp = (blockIdx.x * blockDim.x + threadIdx.x) >> 5;
    int lane = threadIdx.x & 31;
    if (warp >= NN) return;
    int node = warp;
    int rs = g_rowptr[node], re = g_rowptr[node + 1];
    float di = g_dinv[node];
    const float2* g2 = reinterpret_cast<const float2*>(g);
    float2 gv = g2[(size_t)node * 32 + lane];
    float nself = di * di;
    float2 acc = make_float2(nself * gv.x, nself * gv.y);
    for (int j = rs; j < re; j++) {
        int src = g_csrc[j];
        float nrm = di * g_dinv[src];
        float2 v = g2[(size_t)src * 32 + lane];
        acc.x += nrm * v.x; acc.y += nrm * v.y;
    }
    float2 bv = reinterpret_cast<const float2*>(bias)[lane];
    reinterpret_cast<float2*>(z)[(size_t)node * 32 + lane] =
        make_float2(acc.x + bv.x, acc.y + bv.y);
}

// ---------------- decode: out[e] = dot(z[a], z[b]), 8 lanes/edge ----------------
__global__ void decode_kernel(const int* __restrict__ eli, float* __restrict__ out) {
    int gtid = blockIdx.x * blockDim.x + threadIdx.x;
    int warp = gtid >> 5;
    int lane = threadIdx.x & 31;
    int sub = lane >> 3, l8 = lane & 7;
    int e = warp * 4 + sub;
    if (e >= NLL) return;
    int a = eli[e];
    int b = eli[NLL + e];
    const float4* z4 = reinterpret_cast<const float4*>(g_zbuf);
    float4 va0 = z4[(size_t)a * 16 + l8];
    float4 va1 = z4[(size_t)a * 16 + 8 + l8];
    float4 vb0 = z4[(size_t)b * 16 + l8];
    float4 vb1 = z4[(size_t)b * 16 + 8 + l8];
    float dot = va0.x * vb0.x + va0.y * vb0.y + va0.z * vb0.z + va0.w * vb0.w
              + va1.x * vb1.x + va1.y * vb1.y + va1.z * vb1.z + va1.w * vb1.w;
    dot += __shfl_xor_sync(0xffffffffu, dot, 4);
    dot += __shfl_xor_sync(0xffffffffu, dot, 2);
    dot += __shfl_xor_sync(0xffffffffu, dot, 1);
    if (l8 == 0) out[e] = dot;
}

// ---------------- launch ----------------
extern "C" void kernel_launch(void* const* d_in, const int* in_sizes, int n_in,
                              void* d_out, int out_size) {
    const float* x   = (const float*)d_in[0];
    const int*   ei  = (const int*)d_in[1];          // [2,E]
    const int*   eli = (const int*)d_in[2];          // [2,NL]
    const float* W1  = (const float*)d_in[3];
    const float* a1s = (const float*)d_in[4];
    const float* a1d = (const float*)d_in[5];
    const float* b1  = (const float*)d_in[6];
    const float* W2  = (const float*)d_in[7];
    const float* a2s = (const float*)d_in[8];
    const float* a2d = (const float*)d_in[9];
    const float* b2  = (const float*)d_in[10];
    const float* W3  = (const float*)d_in[11];
    const float* a3s = (const float*)d_in[12];
    const float* a3d = (const float*)d_in[13];
    const float* b3  = (const float*)d_in[14];
    const float* W4  = (const float*)d_in[15];
    const float* b4  = (const float*)d_in[16];
    float* out = (float*)d_out;

    const int* e_src = ei;
    const int* e_dst = ei + EE;

    float *bufA, *bufB, *zbuf;
    cudaGetSymbolAddress((void**)&bufA, g_bufA);
    cudaGetSymbolAddress((void**)&bufB, g_bufB);
    cudaGetSymbolAddress((void**)&zbuf, g_zbuf);

    const int TB = 256;
    dim3 gemm_block(128);
    dim3 gemm_grid_h((NN + 127) / 128, HIDD / 64);   // N=128 output cols
    dim3 gemm_grid_o((NN + 127) / 128, DOUT / 64);   // N=64 output cols
    int node_warp_blocks = (NN * 32 + TB - 1) / TB;
    int edge_blocks = (EE + TB - 1) / TB;

    // ---- CSR build ----
    zero_kernel<<<(NN + TB - 1) / TB, TB>>>();
    count_deg_kernel<<<edge_blocks, TB>>>(e_dst);
    scan_kernel<<<1, 1024>>>();
    fill_csr_kernel<<<edge_blocks, TB>>>(e_src, e_dst);
    dinv_kernel<<<(NN + TB - 1) / TB, TB>>>();

    // ---- layer 1 ----
    sgemm_kernel<<<gemm_grid_h, gemm_block>>>(NN, HIDD, DIN, x, W1, bufA);
    scores_kernel<<<node_warp_blocks, TB>>>(bufA, a1s, a1d);
    gat_agg_kernel<<<node_warp_blocks, TB>>>(bufA, b1, bufB);

    // ---- layer 2 ----
    sgemm_kernel<<<gemm_grid_h, gemm_block>>>(NN, HIDD, HIDD, bufB, W2, bufA);
    scores_kernel<<<node_warp_blocks, TB>>>(bufA, a2s, a2d);
    gat_agg_kernel<<<node_warp_blocks, TB>>>(bufA, b2, bufB);

    // ---- layer 3 ----
    sgemm_kernel<<<gemm_grid_h, gemm_block>>>(NN, HIDD, HIDD, bufB, W3, bufA);
    scores_kernel<<<node_warp_blocks, TB>>>(bufA, a3s, a3d);
    gat_agg_kernel<<<node_warp_blocks, TB>>>(bufA, b3, bufB);

    // ---- GCN ----
    sgemm_kernel<<<gemm_grid_o, gemm_block>>>(NN, DOUT, HIDD, bufB, W4, bufA);
    gcn_agg_kernel<<<node_warp_blocks, TB>>>(bufA, b4, zbuf);

    // ---- decode ----
    int dec_warps = (NLL + 3) / 4;
    int dec_blocks = (dec_warps * 32 + TB - 1) / TB;
    decode_kernel<<<dec_blocks, TB>>>(eli, out);
}

// round 3
// speedup vs baseline: 1.1744x; 1.1744x over previous
#include <cuda_runtime.h>
#include <math.h>

#define NN   50000
#define EE   1600000
#define DIN  128
#define HIDD 128
#define DOUT 64
#define NLL  200000
#define NEG  0.2f

#define SCAN_B 512
#define NBLK   ((NN + SCAN_B - 1) / SCAN_B)   // 98

// ---------------- scratch (device globals; no allocation allowed) ----------------
__device__ float g_bufA[NN * HIDD];
__device__ float g_bufB[NN * HIDD];
__device__ float g_zbuf[NN * DOUT];
__device__ float g_as[NN];
__device__ float g_ad[NN];
__device__ float g_dinv[NN];
__device__ float g_ep[EE];
__device__ int   g_deg[NN];
__device__ int   g_cursor[NN];
__device__ int   g_rowptr[NN + 1];
__device__ int   g_csrc[EE];
__device__ int   g_bsum[NBLK];
__device__ int   g_boff[NBLK];

__device__ __forceinline__ float lrelu(float v) { return v > 0.f ? v : NEG * v; }

// ---------------- CSR build ----------------
__global__ void zero_kernel() {
    int i = blockIdx.x * blockDim.x + threadIdx.x;
    if (i < NN) { g_deg[i] = 0; g_cursor[i] = 0; }
}

__global__ void count_deg_kernel(const int* __restrict__ dst) {
    int i = blockIdx.x * blockDim.x + threadIdx.x;
    if (i < EE) atomicAdd(&g_deg[dst[i]], 1);
}

// block-level exclusive scan of g_deg -> g_rowptr (local), block totals -> g_bsum
__global__ void scan_partial_kernel() {
    __shared__ int ws[SCAN_B / 32];           // 16
    int tid = threadIdx.x;
    int lane = tid & 31, wid = tid >> 5;
    int i = blockIdx.x * SCAN_B + tid;
    int v = (i < NN) ? g_deg[i] : 0;
    int x = v;
    #pragma unroll
    for (int o = 1; o < 32; o <<= 1) {
        int y = __shfl_up_sync(0xffffffffu, x, o);
        if (lane >= o) x += y;
    }
    if (lane == 31) ws[wid] = x;
    __syncthreads();
    if (tid < 32) {                           // FULL warp participates in shuffles
        int w = (tid < SCAN_B / 32) ? ws[tid] : 0;
        #pragma unroll
        for (int o = 1; o < SCAN_B / 32; o <<= 1) {
            int y = __shfl_up_sync(0xffffffffu, w, o);
            if (tid >= o) w += y;
        }
        if (tid < SCAN_B / 32) ws[tid] = w;
    }
    __syncthreads();
    int pref = wid ? ws[wid - 1] : 0;
    int incl = x + pref;
    if (i < NN) g_rowptr[i] = incl - v;         // exclusive, block-local
    if (tid == SCAN_B - 1) g_bsum[blockIdx.x] = incl;
}

__global__ void scan_bsum_kernel() {   // 1 block, 128 threads (NBLK <= 128)
    __shared__ int ws[4];
    int tid = threadIdx.x;
    int lane = tid & 31, wid = tid >> 5;
    int v = (tid < NBLK) ? g_bsum[tid] : 0;
    int x = v;
    #pragma unroll
    for (int o = 1; o < 32; o <<= 1) {
        int y = __shfl_up_sync(0xffffffffu, x, o);
        if (lane >= o) x += y;
    }
    if (lane == 31) ws[wid] = x;
    __syncthreads();
    if (tid < 32) {                           // FULL warp participates in shuffles
        int w = (tid < 4) ? ws[tid] : 0;
        #pragma unroll
        for (int o = 1; o < 4; o <<= 1) {
            int y = __shfl_up_sync(0xffffffffu, w, o);
            if (tid >= o) w += y;
        }
        if (tid < 4) ws[tid] = w;
    }
    __syncthreads();
    int pref = wid ? ws[wid - 1] : 0;
    int incl = x + pref;
    if (tid < NBLK) g_boff[tid] = incl - v;      // exclusive
    if (tid == 127) g_rowptr[NN] = incl;         // total = EE
}

__global__ void scan_add_kernel() {
    int i = blockIdx.x * blockDim.x + threadIdx.x;
    if (i < NN) g_rowptr[i] += g_boff[i / SCAN_B];
}

__global__ void fill_csr_kernel(const int* __restrict__ src, const int* __restrict__ dst) {
    int i = blockIdx.x * blockDim.x + threadIdx.x;
    if (i < EE) {
        int d = dst[i];
        int pos = atomicAdd(&g_cursor[d], 1);
        g_csrc[g_rowptr[d] + pos] = src[i];
    }
}

__global__ void dinv_kernel() {
    int i = blockIdx.x * blockDim.x + threadIdx.x;
    if (i < NN) g_dinv[i] = rsqrtf((float)(g_deg[i] + 1));
}

// ---------------- SGEMM: C[M,BN] = A[M,128] * B[128,BN], optional fused scores ----------------
// BM=128, BK=16, 256 threads, TM=8, TN=BN/16. BN covers the full output width.
template<int BN, bool FUSE>
__global__ __launch_bounds__(256)
void sgemm128_kernel(const float* __restrict__ A, const float* __restrict__ B,
                     float* __restrict__ C,
                     const float* __restrict__ avs, const float* __restrict__ avd) {
    constexpr int TN = BN / 16;
    __shared__ float As[16][132];     // padded: 132*4=528 bytes/row, 16B-aligned
    __shared__ float Bs[16][BN];
    const int tid = threadIdx.x;
    const int block_row = blockIdx.x * 128;
    const int tr = tid >> 4;          // 0..15
    const int tc = tid & 15;          // 0..15
    float acc[8][TN];
    #pragma unroll
    for (int i = 0; i < 8; i++)
        #pragma unroll
        for (int j = 0; j < TN; j++) acc[i][j] = 0.f;

    const int aRow = tid >> 2;               // 0..63
    const int aCol = (tid & 3) << 2;         // 0,4,8,12

    #pragma unroll 2
    for (int k0 = 0; k0 < 128; k0 += 16) {
        #pragma unroll
        for (int i = 0; i < 2; i++) {
            int r = aRow + i * 64;
            int grow = block_row + r;
            float4 v = make_float4(0.f, 0.f, 0.f, 0.f);
            if (grow < NN)
                v = *reinterpret_cast<const float4*>(&A[(size_t)grow * 128 + k0 + aCol]);
            As[aCol + 0][r] = v.x;
            As[aCol + 1][r] = v.y;
            As[aCol + 2][r] = v.z;
            As[aCol + 3][r] = v.w;
        }
        if (BN == 128) {
            #pragma unroll
            for (int i = 0; i < 2; i++) {
                int r = (tid >> 5) + i * 8;
                int c = (tid & 31) * 4;
                *reinterpret_cast<float4*>(&Bs[r][c]) =
                    *reinterpret_cast<const float4*>(&B[(size_t)(k0 + r) * BN + c]);
            }
        } else {
            int r = tid >> 4;
            int c = (tid & 15) * 4;
            *reinterpret_cast<float4*>(&Bs[r][c]) =
                *reinterpret_cast<const float4*>(&B[(size_t)(k0 + r) * BN + c]);
        }
        __syncthreads();
        #pragma unroll
        for (int kk = 0; kk < 16; kk++) {
            float ra[8], rb[TN];
            *reinterpret_cast<float4*>(&ra[0]) = *reinterpret_cast<float4*>(&As[kk][tr * 8]);
            *reinterpret_cast<float4*>(&ra[4]) = *reinterpret_cast<float4*>(&As[kk][tr * 8 + 4]);
            #pragma unroll
            for (int j4 = 0; j4 < TN / 4; j4++)
                *reinterpret_cast<float4*>(&rb[j4 * 4]) =
                    *reinterpret_cast<float4*>(&Bs[kk][tc * TN + j4 * 4]);
            #pragma unroll
            for (int i = 0; i < 8; i++)
                #pragma unroll
                for (int j = 0; j < TN; j++)
                    acc[i][j] = fmaf(ra[i], rb[j], acc[i][j]);
        }
        __syncthreads();
    }

    #pragma unroll
    for (int i = 0; i < 8; i++) {
        int grow = block_row + tr * 8 + i;
        if (grow < NN) {
            #pragma unroll
            for (int j4 = 0; j4 < TN / 4; j4++) {
                float4 v = make_float4(acc[i][j4 * 4 + 0], acc[i][j4 * 4 + 1],
                                       acc[i][j4 * 4 + 2], acc[i][j4 * 4 + 3]);
                *reinterpret_cast<float4*>(&C[(size_t)grow * BN + tc * TN + j4 * 4]) = v;
            }
        }
    }

    if (FUSE) {
        float avsr[TN], avdr[TN];
        #pragma unroll
        for (int j = 0; j < TN; j++) {
            avsr[j] = avs[tc * TN + j];
            avdr[j] = avd[tc * TN + j];
        }
        #pragma unroll
        for (int i = 0; i < 8; i++) {
            float s = 0.f, d = 0.f;
            #pragma unroll
            for (int j = 0; j < TN; j++) {
                s = fmaf(acc[i][j], avsr[j], s);
                d = fmaf(acc[i][j], avdr[j], d);
            }
            #pragma unroll
            for (int mk = 1; mk < 16; mk <<= 1) {
                s += __shfl_xor_sync(0xffffffffu, s, mk);
                d += __shfl_xor_sync(0xffffffffu, d, mk);
            }
            if (tc == 0) {
                int grow = block_row + tr * 8 + i;
                if (grow < NN) { g_as[grow] = s; g_ad[grow] = d; }
            }
        }
    }
}

// ---------------- GAT aggregate (warp per dst node), cached edge probabilities ----------------
__global__ void gat_agg_kernel(const float* __restrict__ h,
                               const float* __restrict__ bias,
                               float* __restrict__ out) {
    int warp = (blockIdx.x * blockDim.x + threadIdx.x) >> 5;
    int lane = threadIdx.x & 31;
    if (warp >= NN) return;
    int node = warp;
    int rs = g_rowptr[node], re = g_rowptr[node + 1];
    float adi = g_ad[node];
    float self_e = lrelu(g_as[node] + adi);

    // pass 1: compute scores (write to g_ep, coalesced), track max
    float m = self_e;
    for (int j = rs + lane; j < re; j += 32) {
        float e = lrelu(g_as[g_csrc[j]] + adi);
        g_ep[j] = e;
        m = fmaxf(m, e);
    }
    #pragma unroll
    for (int o = 16; o; o >>= 1) m = fmaxf(m, __shfl_xor_sync(0xffffffffu, m, o));

    // pass 2: p = exp(e - m), overwrite g_ep (lane-private indices), sum
    float ssum = 0.f;
    for (int j = rs + lane; j < re; j += 32) {
        float p = __expf(g_ep[j] - m);
        g_ep[j] = p;
        ssum += p;
    }
    #pragma unroll
    for (int o = 16; o; o >>= 1) ssum += __shfl_xor_sync(0xffffffffu, ssum, o);
    float pself = __expf(self_e - m);
    ssum += pself;

    // pass 3: weighted accumulate with register-staged chunks (lane-private re-reads)
    const float4* h4 = reinterpret_cast<const float4*>(h);
    float4 hv = h4[(size_t)node * 32 + lane];
    float4 acc = make_float4(pself * hv.x, pself * hv.y, pself * hv.z, pself * hv.w);
    for (int base = rs; base < re; base += 32) {
        int j = base + lane;
        int srcv = 0; float pv = 0.f;
        if (j < re) { srcv = g_csrc[j]; pv = g_ep[j]; }
        int cnt = re - base;
        if (cnt >= 32) {
            #pragma unroll
            for (int t = 0; t < 32; t++) {
                int s = __shfl_sync(0xffffffffu, srcv, t);
                float p = __shfl_sync(0xffffffffu, pv, t);
                float4 v = h4[(size_t)s * 32 + lane];
                acc.x = fmaf(p, v.x, acc.x);
                acc.y = fmaf(p, v.y, acc.y);
                acc.z = fmaf(p, v.z, acc.z);
                acc.w = fmaf(p, v.w, acc.w);
            }
        } else {
            for (int t = 0; t < cnt; t++) {
                int s = __shfl_sync(0xffffffffu, srcv, t);
                float p = __shfl_sync(0xffffffffu, pv, t);
                float4 v = h4[(size_t)s * 32 + lane];
                acc.x = fmaf(p, v.x, acc.x);
                acc.y = fmaf(p, v.y, acc.y);
                acc.z = fmaf(p, v.z, acc.z);
                acc.w = fmaf(p, v.w, acc.w);
            }
        }
    }
    float inv = 1.f / ssum;
    float4 bv = reinterpret_cast<const float4*>(bias)[lane];
    float4 o;
    o.x = fmaxf(fmaf(acc.x, inv, bv.x), 0.f);
    o.y = fmaxf(fmaf(acc.y, inv, bv.y), 0.f);
    o.z = fmaxf(fmaf(acc.z, inv, bv.z), 0.f);
    o.w = fmaxf(fmaf(acc.w, inv, bv.w), 0.f);
    reinterpret_cast<float4*>(out)[(size_t)node * 32 + lane] = o;
}

// ---------------- GCN aggregate (warp per dst node), OUT=64 (float2/lane) ----------------
__global__ void gcn_agg_kernel(const float* __restrict__ g,
                               const float* __restrict__ bias,
                               float* __restrict__ z) {
    int warp = (blockIdx.x * blockDim.x + threadIdx.x) >> 5;
    int lane = threadIdx.x & 31;
    if (warp >= NN) return;
    int node = warp;
    int rs = g_rowptr[node], re = g_rowptr[node + 1];
    float di = g_dinv[node];
    const float2* g2 = reinterpret_cast<const float2*>(g);
    float2 gv = g2[(size_t)node * 32 + lane];
    float nself = di * di;
    float2 acc = make_float2(nself * gv.x, nself * gv.y);
    for (int base = rs; base < re; base += 32) {
        int j = base + lane;
        int srcv = 0; float dv = 0.f;
        if (j < re) { srcv = g_csrc[j]; dv = g_dinv[srcv]; }
        int cnt = re - base;
        if (cnt >= 32) {
            #pragma unroll
            for (int t = 0; t < 32; t++) {
                int s = __shfl_sync(0xffffffffu, srcv, t);
                float nd = __shfl_sync(0xffffffffu, dv, t);
                float nrm = di * nd;
                float2 v = g2[(size_t)s * 32 + lane];
                acc.x = fmaf(nrm, v.x, acc.x);
                acc.y = fmaf(nrm, v.y, acc.y);
            }
        } else {
            for (int t = 0; t < cnt; t++) {
                int s = __shfl_sync(0xffffffffu, srcv, t);
                float nd = __shfl_sync(0xffffffffu, dv, t);
                float nrm = di * nd;
                float2 v = g2[(size_t)s * 32 + lane];
                acc.x = fmaf(nrm, v.x, acc.x);
                acc.y = fmaf(nrm, v.y, acc.y);
            }
        }
    }
    float2 bv = reinterpret_cast<const float2*>(bias)[lane];
    reinterpret_cast<float2*>(z)[(size_t)node * 32 + lane] =
        make_float2(acc.x + bv.x, acc.y + bv.y);
}

// ---------------- decode: out[e] = dot(z[a], z[b]), 8 lanes/edge ----------------
__global__ void decode_kernel(const int* __restrict__ eli, float* __restrict__ out) {
    int gtid = blockIdx.x * blockDim.x + threadIdx.x;
    int warp = gtid >> 5;
    int lane = threadIdx.x & 31;
    int sub = lane >> 3, l8 = lane & 7;
    int e = warp * 4 + sub;
    if (e >= NLL) return;
    int a = eli[e];
    int b = eli[NLL + e];
    const float4* z4 = reinterpret_cast<const float4*>(g_zbuf);
    float4 va0 = z4[(size_t)a * 16 + l8];
    float4 va1 = z4[(size_t)a * 16 + 8 + l8];
    float4 vb0 = z4[(size_t)b * 16 + l8];
    float4 vb1 = z4[(size_t)b * 16 + 8 + l8];
    float dot = va0.x * vb0.x + va0.y * vb0.y + va0.z * vb0.z + va0.w * vb0.w
              + va1.x * vb1.x + va1.y * vb1.y + va1.z * vb1.z + va1.w * vb1.w;
    dot += __shfl_xor_sync(0xffffffffu, dot, 4);
    dot += __shfl_xor_sync(0xffffffffu, dot, 2);
    dot += __shfl_xor_sync(0xffffffffu, dot, 1);
    if (l8 == 0) out[e] = dot;
}

// ---------------- launch ----------------
extern "C" void kernel_launch(void* const* d_in, const int* in_sizes, int n_in,
                              void* d_out, int out_size) {
    const float* x   = (const float*)d_in[0];
    const int*   ei  = (const int*)d_in[1];          // [2,E]
    const int*   eli = (const int*)d_in[2];          // [2,NL]
    const float* W1  = (const float*)d_in[3];
    const float* a1s = (const float*)d_in[4];
    const float* a1d = (const float*)d_in[5];
    const float* b1  = (const float*)d_in[6];
    const float* W2  = (const float*)d_in[7];
    const float* a2s = (const float*)d_in[8];
    const float* a2d = (const float*)d_in[9];
    const float* b2  = (const float*)d_in[10];
    const float* W3  = (const float*)d_in[11];
    const float* a3s = (const float*)d_in[12];
    const float* a3d = (const float*)d_in[13];
    const float* b3  = (const float*)d_in[14];
    const float* W4  = (const float*)d_in[15];
    const float* b4  = (const float*)d_in[16];
    float* out = (float*)d_out;

    const int* e_src = ei;
    const int* e_dst = ei + EE;

    float *bufA, *bufB, *zbuf;
    cudaGetSymbolAddress((void**)&bufA, g_bufA);
    cudaGetSymbolAddress((void**)&bufB, g_bufB);
    cudaGetSymbolAddress((void**)&zbuf, g_zbuf);

    const int TB = 256;
    dim3 gemm_grid((NN + 127) / 128);
    int node_warp_blocks = (NN * 32 + TB - 1) / TB;
    int edge_blocks = (EE + TB - 1) / TB;
    int node_blocks = (NN + TB - 1) / TB;

    // ---- CSR build ----
    zero_kernel<<<node_blocks, TB>>>();
    count_deg_kernel<<<edge_blocks, TB>>>(e_dst);
    scan_partial_kernel<<<NBLK, SCAN_B>>>();
    scan_bsum_kernel<<<1, 128>>>();
    scan_add_kernel<<<node_blocks, TB>>>();
    fill_csr_kernel<<<edge_blocks, TB>>>(e_src, e_dst);
    dinv_kernel<<<node_blocks, TB>>>();

    // ---- layer 1 ----
    sgemm128_kernel<HIDD, true><<<gemm_grid, 256>>>(x, W1, bufA, a1s, a1d);
    gat_agg_kernel<<<node_warp_blocks, TB>>>(bufA, b1, bufB);

    // ---- layer 2 ----
    sgemm128_kernel<HIDD, true><<<gemm_grid, 256>>>(bufB, W2, bufA, a2s, a2d);
    gat_agg_kernel<<<node_warp_blocks, TB>>>(bufA, b2, bufB);

    // ---- layer 3 ----
    sgemm128_kernel<HIDD, true><<<gemm_grid, 256>>>(bufB, W3, bufA, a3s, a3d);
    gat_agg_kernel<<<node_warp_blocks, TB>>>(bufA, b3, bufB);

    // ---- GCN ----
    sgemm128_kernel<DOUT, false><<<gemm_grid, 256>>>(bufB, W4, bufA, nullptr, nullptr);
    gcn_agg_kernel<<<node_warp_blocks, TB>>>(bufA, b4, zbuf);

    // ---- decode ----
    int dec_warps = (NLL + 3) / 4;
    int dec_blocks = (dec_warps * 32 + TB - 1) / TB;
    decode_kernel<<<dec_blocks, TB>>>(eli, out);
}

// round 4
// speedup vs baseline: 1.2364x; 1.0528x over previous
#include <cuda_runtime.h>
#include <math.h>

#define NN   50000
#define EE   1600000
#define DIN  128
#define HIDD 128
#define DOUT 64
#define NLL  200000
#define NEG  0.2f

#define SCAN_B 512
#define NBLK   ((NN + SCAN_B - 1) / SCAN_B)   // 98
#define GEMM_BLOCKS ((NN + 127) / 128)        // 391
#define E4_BLOCKS   ((EE / 4 + 255) / 256)    // 1563
#define DEC_BLOCKS  (((NLL + 3) / 4 * 32 + 255) / 256)
#define ZERO_BLOCKS 32

// ---------------- scratch (device globals; no allocation allowed) ----------------
__device__ float g_bufA[NN * HIDD];
__device__ float g_bufB[NN * HIDD];
__device__ float g_zbuf[NN * DOUT];
__device__ float g_as[NN];
__device__ float g_ad[NN];
__device__ float g_dinv[NN];
__device__ float g_ep[EE];
__device__ int   g_deg[NN];        // zero-initialized at load; re-zeroed by decode
__device__ int   g_cursor[NN];     // same
__device__ int   g_rowptr[NN + 1];
__device__ int   g_csrc[EE];
__device__ int   g_bsum[NBLK];
__device__ int   g_boff[NBLK];

__device__ __forceinline__ float lrelu(float v) { return v > 0.f ? v : NEG * v; }

// ---------------- scan: block partials (+ fused dinv) ----------------
__global__ void scan_partial_kernel() {
    __shared__ int ws[SCAN_B / 32];           // 16
    int tid = threadIdx.x;
    int lane = tid & 31, wid = tid >> 5;
    int i = blockIdx.x * SCAN_B + tid;
    int v = (i < NN) ? g_deg[i] : 0;
    if (i < NN) g_dinv[i] = rsqrtf((float)(v + 1));   // fused dinv
    int x = v;
    #pragma unroll
    for (int o = 1; o < 32; o <<= 1) {
        int y = __shfl_up_sync(0xffffffffu, x, o);
        if (lane >= o) x += y;
    }
    if (lane == 31) ws[wid] = x;
    __syncthreads();
    if (tid < 32) {                           // FULL warp participates in shuffles
        int w = (tid < SCAN_B / 32) ? ws[tid] : 0;
        #pragma unroll
        for (int o = 1; o < SCAN_B / 32; o <<= 1) {
            int y = __shfl_up_sync(0xffffffffu, w, o);
            if (tid >= o) w += y;
        }
        if (tid < SCAN_B / 32) ws[tid] = w;
    }
    __syncthreads();
    int pref = wid ? ws[wid - 1] : 0;
    int incl = x + pref;
    if (i < NN) g_rowptr[i] = incl - v;         // exclusive, block-local
    if (tid == SCAN_B - 1) g_bsum[blockIdx.x] = incl;
}

__global__ void scan_bsum_kernel() {   // 1 block, 128 threads (NBLK <= 128)
    __shared__ int ws[4];
    int tid = threadIdx.x;
    int lane = tid & 31, wid = tid >> 5;
    int v = (tid < NBLK) ? g_bsum[tid] : 0;
    int x = v;
    #pragma unroll
    for (int o = 1; o < 32; o <<= 1) {
        int y = __shfl_up_sync(0xffffffffu, x, o);
        if (lane >= o) x += y;
    }
    if (lane == 31) ws[wid] = x;
    __syncthreads();
    if (tid < 32) {                           // FULL warp
        int w = (tid < 4) ? ws[tid] : 0;
        #pragma unroll
        for (int o = 1; o < 4; o <<= 1) {
            int y = __shfl_up_sync(0xffffffffu, w, o);
            if (tid >= o) w += y;
        }
        if (tid < 4) ws[tid] = w;
    }
    __syncthreads();
    int pref = wid ? ws[wid - 1] : 0;
    int incl = x + pref;
    if (tid < NBLK) g_boff[tid] = incl - v;      // exclusive
    if (tid == 127) g_rowptr[NN] = incl;         // total = EE
}

__global__ void scan_add_kernel() {
    int i = blockIdx.x * blockDim.x + threadIdx.x;
    if (i < NN) g_rowptr[i] += g_boff[i / SCAN_B];
}

__global__ void fill_csr_kernel(const int* __restrict__ src, const int* __restrict__ dst) {
    int i = blockIdx.x * blockDim.x + threadIdx.x;
    if (i < EE / 4) {
        int4 s = reinterpret_cast<const int4*>(src)[i];
        int4 d = reinterpret_cast<const int4*>(dst)[i];
        int p;
        p = atomicAdd(&g_cursor[d.x], 1); g_csrc[g_rowptr[d.x] + p] = s.x;
        p = atomicAdd(&g_cursor[d.y], 1); g_csrc[g_rowptr[d.y] + p] = s.y;
        p = atomicAdd(&g_cursor[d.z], 1); g_csrc[g_rowptr[d.z] + p] = s.z;
        p = atomicAdd(&g_cursor[d.w], 1); g_csrc[g_rowptr[d.w] + p] = s.w;
    }
}

// ---------------- SGEMM: C[M,BN] = A[M,128] * B[128,BN], fused scores / fused degree-count ----------------
template<int BN, bool FUSE, bool COUNT>
__global__ __launch_bounds__(256)
void sgemm128_kernel(const float* __restrict__ A, const float* __restrict__ B,
                     float* __restrict__ C,
                     const float* __restrict__ avs, const float* __restrict__ avd,
                     const int* __restrict__ edst) {
    if (COUNT && blockIdx.x >= GEMM_BLOCKS) {
        // overlapped degree count (latency-bound; hides behind FMA-bound GEMM blocks)
        int i = (blockIdx.x - GEMM_BLOCKS) * 256 + threadIdx.x;
        if (i < EE / 4) {
            int4 d = reinterpret_cast<const int4*>(edst)[i];
            atomicAdd(&g_deg[d.x], 1);
            atomicAdd(&g_deg[d.y], 1);
            atomicAdd(&g_deg[d.z], 1);
            atomicAdd(&g_deg[d.w], 1);
        }
        return;
    }
    constexpr int TN = BN / 16;
    __shared__ float As[16][132];     // padded: 16B-aligned rows
    __shared__ float Bs[16][BN];
    const int tid = threadIdx.x;
    const int block_row = blockIdx.x * 128;
    const int tr = tid >> 4;          // 0..15
    const int tc = tid & 15;          // 0..15
    float acc[8][TN];
    #pragma unroll
    for (int i = 0; i < 8; i++)
        #pragma unroll
        for (int j = 0; j < TN; j++) acc[i][j] = 0.f;

    const int aRow = tid >> 2;               // 0..63
    const int aCol = (tid & 3) << 2;         // 0,4,8,12

    #pragma unroll 2
    for (int k0 = 0; k0 < 128; k0 += 16) {
        #pragma unroll
        for (int i = 0; i < 2; i++) {
            int r = aRow + i * 64;
            int grow = block_row + r;
            float4 v = make_float4(0.f, 0.f, 0.f, 0.f);
            if (grow < NN)
                v = *reinterpret_cast<const float4*>(&A[(size_t)grow * 128 + k0 + aCol]);
            As[aCol + 0][r] = v.x;
            As[aCol + 1][r] = v.y;
            As[aCol + 2][r] = v.z;
            As[aCol + 3][r] = v.w;
        }
        if (BN == 128) {
            #pragma unroll
            for (int i = 0; i < 2; i++) {
                int r = (tid >> 5) + i * 8;
                int c = (tid & 31) * 4;
                *reinterpret_cast<float4*>(&Bs[r][c]) =
                    *reinterpret_cast<const float4*>(&B[(size_t)(k0 + r) * BN + c]);
            }
        } else {
            int r = tid >> 4;
            int c = (tid & 15) * 4;
            *reinterpret_cast<float4*>(&Bs[r][c]) =
                *reinterpret_cast<const float4*>(&B[(size_t)(k0 + r) * BN + c]);
        }
        __syncthreads();
        #pragma unroll
        for (int kk = 0; kk < 16; kk++) {
            float ra[8], rb[TN];
            *reinterpret_cast<float4*>(&ra[0]) = *reinterpret_cast<float4*>(&As[kk][tr * 8]);
            *reinterpret_cast<float4*>(&ra[4]) = *reinterpret_cast<float4*>(&As[kk][tr * 8 + 4]);
            #pragma unroll
            for (int j4 = 0; j4 < TN / 4; j4++)
                *reinterpret_cast<float4*>(&rb[j4 * 4]) =
                    *reinterpret_cast<float4*>(&Bs[kk][tc * TN + j4 * 4]);
            #pragma unroll
            for (int i = 0; i < 8; i++)
                #pragma unroll
                for (int j = 0; j < TN; j++)
                    acc[i][j] = fmaf(ra[i], rb[j], acc[i][j]);
        }
        __syncthreads();
    }

    #pragma unroll
    for (int i = 0; i < 8; i++) {
        int grow = block_row + tr * 8 + i;
        if (grow < NN) {
            #pragma unroll
            for (int j4 = 0; j4 < TN / 4; j4++) {
                float4 v = make_float4(acc[i][j4 * 4 + 0], acc[i][j4 * 4 + 1],
                                       acc[i][j4 * 4 + 2], acc[i][j4 * 4 + 3]);
                *reinterpret_cast<float4*>(&C[(size_t)grow * BN + tc * TN + j4 * 4]) = v;
            }
        }
    }

    if (FUSE) {
        float avsr[TN], avdr[TN];
        #pragma unroll
        for (int j = 0; j < TN; j++) {
            avsr[j] = avs[tc * TN + j];
            avdr[j] = avd[tc * TN + j];
        }
        #pragma unroll
        for (int i = 0; i < 8; i++) {
            float s = 0.f, d = 0.f;
            #pragma unroll
            for (int j = 0; j < TN; j++) {
                s = fmaf(acc[i][j], avsr[j], s);
                d = fmaf(acc[i][j], avdr[j], d);
            }
            #pragma unroll
            for (int mk = 1; mk < 16; mk <<= 1) {
                s += __shfl_xor_sync(0xffffffffu, s, mk);
                d += __shfl_xor_sync(0xffffffffu, d, mk);
            }
            if (tc == 0) {
                int grow = block_row + tr * 8 + i;
                if (grow < NN) { g_as[grow] = s; g_ad[grow] = d; }
            }
        }
    }
}

// ---------------- GAT aggregate (warp per dst node), online softmax, 2 passes ----------------
__global__ void gat_agg_kernel(const float* __restrict__ h,
                               const float* __restrict__ bias,
                               float* __restrict__ out) {
    int warp = (blockIdx.x * blockDim.x + threadIdx.x) >> 5;
    int lane = threadIdx.x & 31;
    if (warp >= NN) return;
    int node = warp;
    int rs = g_rowptr[node], re = g_rowptr[node + 1];
    float adi = g_ad[node];
    float self_e = lrelu(g_as[node] + adi);

    // pass A: compute scores (coalesced write to g_ep), online per-lane (m, s)
    float m_l = self_e;
    float s_l = (lane == 0) ? 1.f : 0.f;      // self term counted once
    for (int j = rs + lane; j < re; j += 32) {
        float e = lrelu(g_as[g_csrc[j]] + adi);
        g_ep[j] = e;
        if (e > m_l) { s_l = fmaf(s_l, __expf(m_l - e), 1.f); m_l = e; }
        else          s_l += __expf(e - m_l);
    }
    float M = m_l;
    #pragma unroll
    for (int o = 16; o; o >>= 1) M = fmaxf(M, __shfl_xor_sync(0xffffffffu, M, o));
    float s_adj = s_l * __expf(m_l - M);      // m_l finite (>= self_e) for all lanes
    #pragma unroll
    for (int o = 16; o; o >>= 1) s_adj += __shfl_xor_sync(0xffffffffu, s_adj, o);
    float ssum = s_adj;
    float pself = __expf(self_e - M);

    // pass B: weighted accumulate with register-staged chunks
    const float4* h4 = reinterpret_cast<const float4*>(h);
    float4 hv = h4[(size_t)node * 32 + lane];
    float4 acc = make_float4(pself * hv.x, pself * hv.y, pself * hv.z, pself * hv.w);
    for (int base = rs; base < re; base += 32) {
        int j = base + lane;
        int srcv = 0; float pv = 0.f;
        if (j < re) { srcv = g_csrc[j]; pv = __expf(g_ep[j] - M); }
        int cnt = re - base;
        if (cnt >= 32) {
            #pragma unroll
            for (int t = 0; t < 32; t++) {
                int s = __shfl_sync(0xffffffffu, srcv, t);
                float p = __shfl_sync(0xffffffffu, pv, t);
                float4 v = h4[(size_t)s * 32 + lane];
                acc.x = fmaf(p, v.x, acc.x);
                acc.y = fmaf(p, v.y, acc.y);
                acc.z = fmaf(p, v.z, acc.z);
                acc.w = fmaf(p, v.w, acc.w);
            }
        } else {
            for (int t = 0; t < cnt; t++) {
                int s = __shfl_sync(0xffffffffu, srcv, t);
                float p = __shfl_sync(0xffffffffu, pv, t);
                float4 v = h4[(size_t)s * 32 + lane];
                acc.x = fmaf(p, v.x, acc.x);
                acc.y = fmaf(p, v.y, acc.y);
                acc.z = fmaf(p, v.z, acc.z);
                acc.w = fmaf(p, v.w, acc.w);
            }
        }
    }
    float inv = 1.f / ssum;
    float4 bv = reinterpret_cast<const float4*>(bias)[lane];
    float4 o;
    o.x = fmaxf(fmaf(acc.x, inv, bv.x), 0.f);
    o.y = fmaxf(fmaf(acc.y, inv, bv.y), 0.f);
    o.z = fmaxf(fmaf(acc.z, inv, bv.z), 0.f);
    o.w = fmaxf(fmaf(acc.w, inv, bv.w), 0.f);
    reinterpret_cast<float4*>(out)[(size_t)node * 32 + lane] = o;
}

// ---------------- GCN aggregate (warp per dst node), OUT=64 (float2/lane) ----------------
__global__ void gcn_agg_kernel(const float* __restrict__ g,
                               const float* __restrict__ bias,
                               float* __restrict__ z) {
    int warp = (blockIdx.x * blockDim.x + threadIdx.x) >> 5;
    int lane = threadIdx.x & 31;
    if (warp >= NN) return;
    int node = warp;
    int rs = g_rowptr[node], re = g_rowptr[node + 1];
    float di = g_dinv[node];
    const float2* g2 = reinterpret_cast<const float2*>(g);
    float2 gv = g2[(size_t)node * 32 + lane];
    float nself = di * di;
    float2 acc = make_float2(nself * gv.x, nself * gv.y);
    for (int base = rs; base < re; base += 32) {
        int j = base + lane;
        int srcv = 0; float dv = 0.f;
        if (j < re) { srcv = g_csrc[j]; dv = g_dinv[srcv]; }
        int cnt = re - base;
        if (cnt >= 32) {
            #pragma unroll
            for (int t = 0; t < 32; t++) {
                int s = __shfl_sync(0xffffffffu, srcv, t);
                float nd = __shfl_sync(0xffffffffu, dv, t);
                float nrm = di * nd;
                float2 v = g2[(size_t)s * 32 + lane];
                acc.x = fmaf(nrm, v.x, acc.x);
                acc.y = fmaf(nrm, v.y, acc.y);
            }
        } else {
            for (int t = 0; t < cnt; t++) {
                int s = __shfl_sync(0xffffffffu, srcv, t);
                float nd = __shfl_sync(0xffffffffu, dv, t);
                float nrm = di * nd;
                float2 v = g2[(size_t)s * 32 + lane];
                acc.x = fmaf(nrm, v.x, acc.x);
                acc.y = fmaf(nrm, v.y, acc.y);
            }
        }
    }
    float2 bv = reinterpret_cast<const float2*>(bias)[lane];
    reinterpret_cast<float2*>(z)[(size_t)node * 32 + lane] =
        make_float2(acc.x + bv.x, acc.y + bv.y);
}

// ---------------- decode + re-zero of deg/cursor for next invocation ----------------
__global__ void decode_kernel(const int* __restrict__ eli, float* __restrict__ out) {
    if (blockIdx.x >= DEC_BLOCKS) {
        int i = (blockIdx.x - DEC_BLOCKS) * 256 + threadIdx.x;
        for (int k = i; k < NN; k += ZERO_BLOCKS * 256) { g_deg[k] = 0; g_cursor[k] = 0; }
        return;
    }
    int gtid = blockIdx.x * blockDim.x + threadIdx.x;
    int warp = gtid >> 5;
    int lane = threadIdx.x & 31;
    int sub = lane >> 3, l8 = lane & 7;
    int e = warp * 4 + sub;
    if (e >= NLL) return;
    int a = eli[e];
    int b = eli[NLL + e];
    const float4* z4 = reinterpret_cast<const float4*>(g_zbuf);
    float4 va0 = z4[(size_t)a * 16 + l8];
    float4 va1 = z4[(size_t)a * 16 + 8 + l8];
    float4 vb0 = z4[(size_t)b * 16 + l8];
    float4 vb1 = z4[(size_t)b * 16 + 8 + l8];
    float dot = va0.x * vb0.x + va0.y * vb0.y + va0.z * vb0.z + va0.w * vb0.w
              + va1.x * vb1.x + va1.y * vb1.y + va1.z * vb1.z + va1.w * vb1.w;
    dot += __shfl_xor_sync(0xffffffffu, dot, 4);
    dot += __shfl_xor_sync(0xffffffffu, dot, 2);
    dot += __shfl_xor_sync(0xffffffffu, dot, 1);
    if (l8 == 0) out[e] = dot;
}

// ---------------- launch ----------------
extern "C" void kernel_launch(void* const* d_in, const int* in_sizes, int n_in,
                              void* d_out, int out_size) {
    const float* x   = (const float*)d_in[0];
    const int*   ei  = (const int*)d_in[1];          // [2,E]
    const int*   eli = (const int*)d_in[2];          // [2,NL]
    const float* W1  = (const float*)d_in[3];
    const float* a1s = (const float*)d_in[4];
    const float* a1d = (const float*)d_in[5];
    const float* b1  = (const float*)d_in[6];
    const float* W2  = (const float*)d_in[7];
    const float* a2s = (const float*)d_in[8];
    const float* a2d = (const float*)d_in[9];
    const float* b2  = (const float*)d_in[10];
    const float* W3  = (const float*)d_in[11];
    const float* a3s = (const float*)d_in[12];
    const float* a3d = (const float*)d_in[13];
    const float* b3  = (const float*)d_in[14];
    const float* W4  = (const float*)d_in[15];
    const float* b4  = (const float*)d_in[16];
    float* out = (float*)d_out;

    const int* e_src = ei;
    const int* e_dst = ei + EE;

    float *bufA, *bufB, *zbuf;
    cudaGetSymbolAddress((void**)&bufA, g_bufA);
    cudaGetSymbolAddress((void**)&bufB, g_bufB);
    cudaGetSymbolAddress((void**)&zbuf, g_zbuf);

    const int TB = 256;
    int node_warp_blocks = (NN * 32 + TB - 1) / TB;
    int node_blocks = (NN + TB - 1) / TB;

    // 0: sgemm1 + fused degree-count (deg/cursor pre-zeroed by previous decode / static init)
    sgemm128_kernel<HIDD, true, true><<<GEMM_BLOCKS + E4_BLOCKS, 256>>>(x, W1, bufA, a1s, a1d, e_dst);
    // 1-3: scan chain (+dinv fused into partial)
    scan_partial_kernel<<<NBLK, SCAN_B>>>();
    scan_bsum_kernel<<<1, 128>>>();
    scan_add_kernel<<<node_blocks, TB>>>();
    // 4: CSR fill
    fill_csr_kernel<<<E4_BLOCKS, TB>>>(e_src, e_dst);
    // 5: gat layer 1  (ncu -s 5 -c 1 profiles this)
    gat_agg_kernel<<<node_warp_blocks, TB>>>(bufA, b1, bufB);

    // layer 2
    sgemm128_kernel<HIDD, true, false><<<GEMM_BLOCKS, 256>>>(bufB, W2, bufA, a2s, a2d, nullptr);
    gat_agg_kernel<<<node_warp_blocks, TB>>>(bufA, b2, bufB);

    // layer 3
    sgemm128_kernel<HIDD, true, false><<<GEMM_BLOCKS, 256>>>(bufB, W3, bufA, a3s, a3d, nullptr);
    gat_agg_kernel<<<node_warp_blocks, TB>>>(bufA, b3, bufB);

    // GCN
    sgemm128_kernel<DOUT, false, false><<<GEMM_BLOCKS, 256>>>(bufB, W4, bufA, nullptr, nullptr, nullptr);
    gcn_agg_kernel<<<node_warp_blocks, TB>>>(bufA, b4, zbuf);

    // decode + re-zero deg/cursor
    decode_kernel<<<DEC_BLOCKS + ZERO_BLOCKS, TB>>>(eli, out);
}

// round 5
// speedup vs baseline: 1.2659x; 1.0239x over previous
#include <cuda_runtime.h>
#include <math.h>

#define NN   50000
#define EE   1600000
#define DIN  128
#define HIDD 128
#define DOUT 64
#define NLL  200000
#define NEG  0.2f

#define SCAN_B 512
#define NBLK   ((NN + SCAN_B - 1) / SCAN_B)   // 98
#define GEMM_BLOCKS ((NN + 127) / 128)        // 391
#define E4_BLOCKS   ((EE / 4 + 255) / 256)    // 1563
#define DEC_BLOCKS  (((NLL + 3) / 4 * 32 + 255) / 256)
#define ZERO_BLOCKS 32

// ---------------- scratch (device globals; no allocation allowed) ----------------
__device__ float g_bufA[NN * HIDD];
__device__ float g_bufB[NN * HIDD];
__device__ float g_zbuf[NN * DOUT];
__device__ float g_as[NN];
__device__ float g_ad[NN];
__device__ float g_dinv[NN];
__device__ float g_ep[EE];
__device__ int   g_deg[NN];        // zero-initialized at load; re-zeroed by decode
__device__ int   g_cursor[NN];     // same
__device__ int   g_rowptr[NN + 1];
__device__ int   g_csrc[EE];
__device__ int   g_bsum[NBLK];
__device__ int   g_boff[NBLK];

__device__ __forceinline__ float lrelu(float v) { return v > 0.f ? v : NEG * v; }

// packed f32x2 helpers
__device__ __forceinline__ unsigned long long pack2(float lo, float hi) {
    unsigned long long r;
    asm("mov.b64 %0, {%1, %2};" : "=l"(r) : "f"(lo), "f"(hi));
    return r;
}
__device__ __forceinline__ void unpack2(unsigned long long v, float& lo, float& hi) {
    asm("mov.b64 {%0, %1}, %2;" : "=f"(lo), "=f"(hi) : "l"(v));
}
__device__ __forceinline__ void fma2(unsigned long long& d,
                                     unsigned long long a, unsigned long long b) {
    asm("fma.rn.f32x2 %0, %1, %2, %0;" : "+l"(d) : "l"(a), "l"(b));
}

// ---------------- scan: block partials (+ fused dinv) ----------------
__global__ void scan_partial_kernel() {
    __shared__ int ws[SCAN_B / 32];           // 16
    int tid = threadIdx.x;
    int lane = tid & 31, wid = tid >> 5;
    int i = blockIdx.x * SCAN_B + tid;
    int v = (i < NN) ? g_deg[i] : 0;
    if (i < NN) g_dinv[i] = rsqrtf((float)(v + 1));   // fused dinv
    int x = v;
    #pragma unroll
    for (int o = 1; o < 32; o <<= 1) {
        int y = __shfl_up_sync(0xffffffffu, x, o);
        if (lane >= o) x += y;
    }
    if (lane == 31) ws[wid] = x;
    __syncthreads();
    if (tid < 32) {                           // FULL warp participates in shuffles
        int w = (tid < SCAN_B / 32) ? ws[tid] : 0;
        #pragma unroll
        for (int o = 1; o < SCAN_B / 32; o <<= 1) {
            int y = __shfl_up_sync(0xffffffffu, w, o);
            if (tid >= o) w += y;
        }
        if (tid < SCAN_B / 32) ws[tid] = w;
    }
    __syncthreads();
    int pref = wid ? ws[wid - 1] : 0;
    int incl = x + pref;
    if (i < NN) g_rowptr[i] = incl - v;         // exclusive, block-local
    if (tid == SCAN_B - 1) g_bsum[blockIdx.x] = incl;
}

__global__ void scan_bsum_kernel() {   // 1 block, 128 threads (NBLK <= 128)
    __shared__ int ws[4];
    int tid = threadIdx.x;
    int lane = tid & 31, wid = tid >> 5;
    int v = (tid < NBLK) ? g_bsum[tid] : 0;
    int x = v;
    #pragma unroll
    for (int o = 1; o < 32; o <<= 1) {
        int y = __shfl_up_sync(0xffffffffu, x, o);
        if (lane >= o) x += y;
    }
    if (lane == 31) ws[wid] = x;
    __syncthreads();
    if (tid < 32) {                           // FULL warp
        int w = (tid < 4) ? ws[tid] : 0;
        #pragma unroll
        for (int o = 1; o < 4; o <<= 1) {
            int y = __shfl_up_sync(0xffffffffu, w, o);
            if (tid >= o) w += y;
        }
        if (tid < 4) ws[tid] = w;
    }
    __syncthreads();
    int pref = wid ? ws[wid - 1] : 0;
    int incl = x + pref;
    if (tid < NBLK) g_boff[tid] = incl - v;      // exclusive
    if (tid == 127) g_rowptr[NN] = incl;         // total = EE
}

__global__ void scan_add_kernel() {
    int i = blockIdx.x * blockDim.x + threadIdx.x;
    if (i < NN) g_rowptr[i] += g_boff[i / SCAN_B];
}

__global__ void fill_csr_kernel(const int* __restrict__ src, const int* __restrict__ dst) {
    int i = blockIdx.x * blockDim.x + threadIdx.x;
    if (i < EE / 4) {
        int4 s = reinterpret_cast<const int4*>(src)[i];
        int4 d = reinterpret_cast<const int4*>(dst)[i];
        int p;
        p = atomicAdd(&g_cursor[d.x], 1); g_csrc[g_rowptr[d.x] + p] = s.x;
        p = atomicAdd(&g_cursor[d.y], 1); g_csrc[g_rowptr[d.y] + p] = s.y;
        p = atomicAdd(&g_cursor[d.z], 1); g_csrc[g_rowptr[d.z] + p] = s.z;
        p = atomicAdd(&g_cursor[d.w], 1); g_csrc[g_rowptr[d.w] + p] = s.w;
    }
}

// ---------------- SGEMM (FFMA2 inner loop): C[M,BN] = A[M,128] * B[128,BN] ----------------
template<int BN, bool FUSE, bool COUNT>
__global__ __launch_bounds__(256)
void sgemm128_kernel(const float* __restrict__ A, const float* __restrict__ B,
                     float* __restrict__ C,
                     const float* __restrict__ avs, const float* __restrict__ avd,
                     const int* __restrict__ edst) {
    if (COUNT && blockIdx.x >= GEMM_BLOCKS) {
        int i = (blockIdx.x - GEMM_BLOCKS) * 256 + threadIdx.x;
        if (i < EE / 4) {
            int4 d = reinterpret_cast<const int4*>(edst)[i];
            atomicAdd(&g_deg[d.x], 1);
            atomicAdd(&g_deg[d.y], 1);
            atomicAdd(&g_deg[d.z], 1);
            atomicAdd(&g_deg[d.w], 1);
        }
        return;
    }
    constexpr int TN = BN / 16;
    constexpr int TN2 = TN / 2;
    __shared__ float As[16][132];     // padded: 16B-aligned rows
    __shared__ float Bs[16][BN];
    const int tid = threadIdx.x;
    const int block_row = blockIdx.x * 128;
    const int tr = tid >> 4;          // 0..15
    const int tc = tid & 15;          // 0..15

    unsigned long long acc2[8][TN2];  // packed fp32 pairs along N
    #pragma unroll
    for (int i = 0; i < 8; i++)
        #pragma unroll
        for (int j = 0; j < TN2; j++) acc2[i][j] = 0ull;

    const int aRow = tid >> 2;               // 0..63
    const int aCol = (tid & 3) << 2;         // 0,4,8,12

    #pragma unroll 2
    for (int k0 = 0; k0 < 128; k0 += 16) {
        #pragma unroll
        for (int i = 0; i < 2; i++) {
            int r = aRow + i * 64;
            int grow = block_row + r;
            float4 v = make_float4(0.f, 0.f, 0.f, 0.f);
            if (grow < NN)
                v = *reinterpret_cast<const float4*>(&A[(size_t)grow * 128 + k0 + aCol]);
            As[aCol + 0][r] = v.x;
            As[aCol + 1][r] = v.y;
            As[aCol + 2][r] = v.z;
            As[aCol + 3][r] = v.w;
        }
        if (BN == 128) {
            #pragma unroll
            for (int i = 0; i < 2; i++) {
                int r = (tid >> 5) + i * 8;
                int c = (tid & 31) * 4;
                *reinterpret_cast<float4*>(&Bs[r][c]) =
                    *reinterpret_cast<const float4*>(&B[(size_t)(k0 + r) * BN + c]);
            }
        } else {
            int r = tid >> 4;
            int c = (tid & 15) * 4;
            *reinterpret_cast<float4*>(&Bs[r][c]) =
                *reinterpret_cast<const float4*>(&B[(size_t)(k0 + r) * BN + c]);
        }
        __syncthreads();
        #pragma unroll
        for (int kk = 0; kk < 16; kk++) {
            float ra[8], rb[TN];
            *reinterpret_cast<float4*>(&ra[0]) = *reinterpret_cast<float4*>(&As[kk][tr * 8]);
            *reinterpret_cast<float4*>(&ra[4]) = *reinterpret_cast<float4*>(&As[kk][tr * 8 + 4]);
            #pragma unroll
            for (int j4 = 0; j4 < TN / 4; j4++)
                *reinterpret_cast<float4*>(&rb[j4 * 4]) =
                    *reinterpret_cast<float4*>(&Bs[kk][tc * TN + j4 * 4]);
            unsigned long long bp[TN2];
            #pragma unroll
            for (int j = 0; j < TN2; j++) bp[j] = pack2(rb[2 * j], rb[2 * j + 1]);
            #pragma unroll
            for (int i = 0; i < 8; i++) {
                unsigned long long ap = pack2(ra[i], ra[i]);
                #pragma unroll
                for (int j = 0; j < TN2; j++)
                    fma2(acc2[i][j], ap, bp[j]);
            }
        }
        __syncthreads();
    }

    // unpack accumulators
    float acc[8][TN];
    #pragma unroll
    for (int i = 0; i < 8; i++)
        #pragma unroll
        for (int j = 0; j < TN2; j++)
            unpack2(acc2[i][j], acc[i][2 * j], acc[i][2 * j + 1]);

    #pragma unroll
    for (int i = 0; i < 8; i++) {
        int grow = block_row + tr * 8 + i;
        if (grow < NN) {
            #pragma unroll
            for (int j4 = 0; j4 < TN / 4; j4++) {
                float4 v = make_float4(acc[i][j4 * 4 + 0], acc[i][j4 * 4 + 1],
                                       acc[i][j4 * 4 + 2], acc[i][j4 * 4 + 3]);
                *reinterpret_cast<float4*>(&C[(size_t)grow * BN + tc * TN + j4 * 4]) = v;
            }
        }
    }

    if (FUSE) {
        float avsr[TN], avdr[TN];
        #pragma unroll
        for (int j = 0; j < TN; j++) {
            avsr[j] = avs[tc * TN + j];
            avdr[j] = avd[tc * TN + j];
        }
        #pragma unroll
        for (int i = 0; i < 8; i++) {
            float s = 0.f, d = 0.f;
            #pragma unroll
            for (int j = 0; j < TN; j++) {
                s = fmaf(acc[i][j], avsr[j], s);
                d = fmaf(acc[i][j], avdr[j], d);
            }
            #pragma unroll
            for (int mk = 1; mk < 16; mk <<= 1) {
                s += __shfl_xor_sync(0xffffffffu, s, mk);
                d += __shfl_xor_sync(0xffffffffu, d, mk);
            }
            if (tc == 0) {
                int grow = block_row + tr * 8 + i;
                if (grow < NN) { g_as[grow] = s; g_ad[grow] = d; }
            }
        }
    }
}

// ---------------- GAT aggregate (warp per dst node), online softmax, 2 passes ----------------
__global__ void gat_agg_kernel(const float* __restrict__ h,
                               const float* __restrict__ bias,
                               float* __restrict__ out) {
    int warp = (blockIdx.x * blockDim.x + threadIdx.x) >> 5;
    int lane = threadIdx.x & 31;
    if (warp >= NN) return;
    int node = warp;
    int rs = g_rowptr[node], re = g_rowptr[node + 1];
    float adi = g_ad[node];
    float self_e = lrelu(g_as[node] + adi);

    // pass A: compute scores (coalesced write to g_ep), online per-lane (m, s)
    float m_l = self_e;
    float s_l = (lane == 0) ? 1.f : 0.f;      // self term counted once
    for (int j = rs + lane; j < re; j += 32) {
        float e = lrelu(g_as[g_csrc[j]] + adi);
        g_ep[j] = e;
        if (e > m_l) { s_l = fmaf(s_l, __expf(m_l - e), 1.f); m_l = e; }
        else          s_l += __expf(e - m_l);
    }
    float M = m_l;
    #pragma unroll
    for (int o = 16; o; o >>= 1) M = fmaxf(M, __shfl_xor_sync(0xffffffffu, M, o));
    float s_adj = s_l * __expf(m_l - M);
    #pragma unroll
    for (int o = 16; o; o >>= 1) s_adj += __shfl_xor_sync(0xffffffffu, s_adj, o);
    float ssum = s_adj;
    float pself = __expf(self_e - M);

    // pass B: weighted accumulate with register-staged chunks
    const float4* h4 = reinterpret_cast<const float4*>(h);
    float4 hv = h4[(size_t)node * 32 + lane];
    float4 acc = make_float4(pself * hv.x, pself * hv.y, pself * hv.z, pself * hv.w);
    for (int base = rs; base < re; base += 32) {
        int j = base + lane;
        int srcv = 0; float pv = 0.f;
        if (j < re) { srcv = g_csrc[j]; pv = __expf(g_ep[j] - M); }
        int cnt = re - base;
        if (cnt >= 32) {
            #pragma unroll
            for (int t = 0; t < 32; t++) {
                int s = __shfl_sync(0xffffffffu, srcv, t);
                float p = __shfl_sync(0xffffffffu, pv, t);
                float4 v = h4[(size_t)s * 32 + lane];
                acc.x = fmaf(p, v.x, acc.x);
                acc.y = fmaf(p, v.y, acc.y);
                acc.z = fmaf(p, v.z, acc.z);
                acc.w = fmaf(p, v.w, acc.w);
            }
        } else {
            for (int t = 0; t < cnt; t++) {
                int s = __shfl_sync(0xffffffffu, srcv, t);
                float p = __shfl_sync(0xffffffffu, pv, t);
                float4 v = h4[(size_t)s * 32 + lane];
                acc.x = fmaf(p, v.x, acc.x);
                acc.y = fmaf(p, v.y, acc.y);
                acc.z = fmaf(p, v.z, acc.z);
                acc.w = fmaf(p, v.w, acc.w);
            }
        }
    }
    float inv = 1.f / ssum;
    float4 bv = reinterpret_cast<const float4*>(bias)[lane];
    float4 o;
    o.x = fmaxf(fmaf(acc.x, inv, bv.x), 0.f);
    o.y = fmaxf(fmaf(acc.y, inv, bv.y), 0.f);
    o.z = fmaxf(fmaf(acc.z, inv, bv.z), 0.f);
    o.w = fmaxf(fmaf(acc.w, inv, bv.w), 0.f);
    reinterpret_cast<float4*>(out)[(size_t)node * 32 + lane] = o;
}

// ---------------- GCN aggregate (warp per dst node), OUT=64 (float2/lane) ----------------
__global__ void gcn_agg_kernel(const float* __restrict__ g,
                               const float* __restrict__ bias,
                               float* __restrict__ z) {
    int warp = (blockIdx.x * blockDim.x + threadIdx.x) >> 5;
    int lane = threadIdx.x & 31;
    if (warp >= NN) return;
    int node = warp;
    int rs = g_rowptr[node], re = g_rowptr[node + 1];
    float di = g_dinv[node];
    const float2* g2 = reinterpret_cast<const float2*>(g);
    float2 gv = g2[(size_t)node * 32 + lane];
    float nself = di * di;
    float2 acc = make_float2(nself * gv.x, nself * gv.y);
    for (int base = rs; base < re; base += 32) {
        int j = base + lane;
        int srcv = 0; float dv = 0.f;
        if (j < re) { srcv = g_csrc[j]; dv = g_dinv[srcv]; }
        int cnt = re - base;
        if (cnt >= 32) {
            #pragma unroll
            for (int t = 0; t < 32; t++) {
                int s = __shfl_sync(0xffffffffu, srcv, t);
                float nd = __shfl_sync(0xffffffffu, dv, t);
                float nrm = di * nd;
                float2 v = g2[(size_t)s * 32 + lane];
                acc.x = fmaf(nrm, v.x, acc.x);
                acc.y = fmaf(nrm, v.y, acc.y);
            }
        } else {
            for (int t = 0; t < cnt; t++) {
                int s = __shfl_sync(0xffffffffu, srcv, t);
                float nd = __shfl_sync(0xffffffffu, dv, t);
                float nrm = di * nd;
                float2 v = g2[(size_t)s * 32 + lane];
                acc.x = fmaf(nrm, v.x, acc.x);
                acc.y = fmaf(nrm, v.y, acc.y);
            }
        }
    }
    float2 bv = reinterpret_cast<const float2*>(bias)[lane];
    reinterpret_cast<float2*>(z)[(size_t)node * 32 + lane] =
        make_float2(acc.x + bv.x, acc.y + bv.y);
}

// ---------------- decode + re-zero of deg/cursor for next invocation ----------------
__global__ void decode_kernel(const int* __restrict__ eli, float* __restrict__ out) {
    if (blockIdx.x >= DEC_BLOCKS) {
        int i = (blockIdx.x - DEC_BLOCKS) * 256 + threadIdx.x;
        for (int k = i; k < NN; k += ZERO_BLOCKS * 256) { g_deg[k] = 0; g_cursor[k] = 0; }
        return;
    }
    int gtid = blockIdx.x * blockDim.x + threadIdx.x;
    int warp = gtid >> 5;
    int lane = threadIdx.x & 31;
    int sub = lane >> 3, l8 = lane & 7;
    int e = warp * 4 + sub;
    if (e >= NLL) return;
    int a = eli[e];
    int b = eli[NLL + e];
    const float4* z4 = reinterpret_cast<const float4*>(g_zbuf);
    float4 va0 = z4[(size_t)a * 16 + l8];
    float4 va1 = z4[(size_t)a * 16 + 8 + l8];
    float4 vb0 = z4[(size_t)b * 16 + l8];
    float4 vb1 = z4[(size_t)b * 16 + 8 + l8];
    float dot = va0.x * vb0.x + va0.y * vb0.y + va0.z * vb0.z + va0.w * vb0.w
              + va1.x * vb1.x + va1.y * vb1.y + va1.z * vb1.z + va1.w * vb1.w;
    dot += __shfl_xor_sync(0xffffffffu, dot, 4);
    dot += __shfl_xor_sync(0xffffffffu, dot, 2);
    dot += __shfl_xor_sync(0xffffffffu, dot, 1);
    if (l8 == 0) out[e] = dot;
}

// ---------------- launch ----------------
extern "C" void kernel_launch(void* const* d_in, const int* in_sizes, int n_in,
                              void* d_out, int out_size) {
    const float* x   = (const float*)d_in[0];
    const int*   ei  = (const int*)d_in[1];          // [2,E]
    const int*   eli = (const int*)d_in[2];          // [2,NL]
    const float* W1  = (const float*)d_in[3];
    const float* a1s = (const float*)d_in[4];
    const float* a1d = (const float*)d_in[5];
    const float* b1  = (const float*)d_in[6];
    const float* W2  = (const float*)d_in[7];
    const float* a2s = (const float*)d_in[8];
    const float* a2d = (const float*)d_in[9];
    const float* b2  = (const float*)d_in[10];
    const float* W3  = (const float*)d_in[11];
    const float* a3s = (const float*)d_in[12];
    const float* a3d = (const float*)d_in[13];
    const float* b3  = (const float*)d_in[14];
    const float* W4  = (const float*)d_in[15];
    const float* b4  = (const float*)d_in[16];
    float* out = (float*)d_out;

    const int* e_src = ei;
    const int* e_dst = ei + EE;

    float *bufA, *bufB, *zbuf;
    cudaGetSymbolAddress((void**)&bufA, g_bufA);
    cudaGetSymbolAddress((void**)&bufB, g_bufB);
    cudaGetSymbolAddress((void**)&zbuf, g_zbuf);

    const int TB = 256;
    int node_warp_blocks = (NN * 32 + TB - 1) / TB;
    int node_blocks = (NN + TB - 1) / TB;

    // 0: sgemm1 + fused degree-count
    sgemm128_kernel<HIDD, true, true><<<GEMM_BLOCKS + E4_BLOCKS, 256>>>(x, W1, bufA, a1s, a1d, e_dst);
    // 1-3: scan chain (+dinv fused into partial)
    scan_partial_kernel<<<NBLK, SCAN_B>>>();
    scan_bsum_kernel<<<1, 128>>>();
    scan_add_kernel<<<node_blocks, TB>>>();
    // 4: CSR fill
    fill_csr_kernel<<<E4_BLOCKS, TB>>>(e_src, e_dst);
    // 5: gat layer 1
    gat_agg_kernel<<<node_warp_blocks, TB>>>(bufA, b1, bufB);

    // layer 2
    sgemm128_kernel<HIDD, true, false><<<GEMM_BLOCKS, 256>>>(bufB, W2, bufA, a2s, a2d, nullptr);
    gat_agg_kernel<<<node_warp_blocks, TB>>>(bufA, b2, bufB);

    // layer 3
    sgemm128_kernel<HIDD, true, false><<<GEMM_BLOCKS, 256>>>(bufB, W3, bufA, a3s, a3d, nullptr);
    gat_agg_kernel<<<node_warp_blocks, TB>>>(bufA, b3, bufB);

    // GCN
    sgemm128_kernel<DOUT, false, false><<<GEMM_BLOCKS, 256>>>(bufB, W4, bufA, nullptr, nullptr, nullptr);
    gcn_agg_kernel<<<node_warp_blocks, TB>>>(bufA, b4, zbuf);

    // decode + re-zero deg/cursor
    decode_kernel<<<DEC_BLOCKS + ZERO_BLOCKS, TB>>>(eli, out);
}